// round 16
// baseline (speedup 1.0000x reference)
#include <cuda_runtime.h>
#include <cuda_fp16.h>
#include <cstdint>

#define NL0 65536
#define NL1 16384
#define NL2 4096
#define NL3 1024
#define NL4 256
#define C   256

#define OFF4 0
#define OFF3 (NL4*C)
#define OFF2 (OFF3 + NL3*C)
#define OFF1 (OFF2 + NL2*C)
#define OFF0 (OFF1 + NL1*C)

#define NCTA 296

__device__ uint32_t g_Bh16[5][32768];
__device__ uint32_t g_Bl16[5][32768];
__device__ float g_coef[5][7 * 256];
__device__ float g_cls4[C];
__device__ float g_xyz1[NL1 * 3];
__device__ float g_xyz2[NL2 * 3];
__device__ float g_xyz3[NL3 * 3];
__device__ float g_xyz4[NL4 * 3];
__device__ int   g_k34[NL3];
__device__ int   g_k23[NL2];
__device__ int   g_k12[NL1];
__device__ unsigned g_sync_cnt;

__device__ __forceinline__ uint32_t smem_u32(const void* p) {
    uint32_t a;
    asm("{ .reg .u64 t; cvta.to.shared.u64 t, %1; cvt.u32.u64 %0, t; }" : "=r"(a) : "l"(p));
    return a;
}
__device__ __forceinline__ void splith(float v, __half& h, __half& l) {
    h = __float2half_rn(v);
    l = __float2half_rn(v - __half2float(h));
}
__device__ __forceinline__ uint32_t packh(__half a, __half b) {
    return (uint32_t)__half_as_ushort(a) | ((uint32_t)__half_as_ushort(b) << 16);
}
__device__ __forceinline__ void split_pair(float v0, float v1, uint32_t& h, uint32_t& l) {
    __half2 hh = __float22half2_rn(make_float2(v0, v1));
    float2 bk = __half22float2(hh);
    __half2 ll = __float22half2_rn(make_float2(v0 - bk.x, v1 - bk.y));
    h = *(uint32_t*)&hh; l = *(uint32_t*)&ll;
}
__device__ __forceinline__ void mma16(float* d, const uint32_t* a, const uint32_t* b) {
    asm volatile("mma.sync.aligned.m16n8k16.row.col.f32.f16.f16.f32 "
        "{%0,%1,%2,%3}, {%4,%5,%6,%7}, {%8,%9}, {%0,%1,%2,%3};"
        : "+f"(d[0]), "+f"(d[1]), "+f"(d[2]), "+f"(d[3])
        : "r"(a[0]), "r"(a[1]), "r"(a[2]), "r"(a[3]), "r"(b[0]), "r"(b[1]));
}
#define LDM4(r, a)                                                                  \
    asm volatile("ldmatrix.sync.aligned.m8n8.x4.shared.b16 {%0,%1,%2,%3}, [%4];"    \
        : "=r"((r)[0]), "=r"((r)[1]), "=r"((r)[2]), "=r"((r)[3]) : "r"(a))

// software grid barrier (all NCTA CTAs co-resident by construction)
__device__ __forceinline__ void grid_sync(unsigned target) {
    __syncthreads();
    if (threadIdx.x == 0) {
        __threadfence();
        atomicAdd(&g_sync_cnt, 1u);
        while (*(volatile unsigned*)&g_sync_cnt < target) { }
        __threadfence();
    }
    __syncthreads();
}

// =============== K1: fused prep (gathers + prep_B x5 + cls4 + barrier reset) ===============
__global__ void __launch_bounds__(256)
prep_all(const float* __restrict__ xyz0,
         const int* __restrict__ idx1, const int* __restrict__ idx2,
         const int* __restrict__ idx3, const int* __restrict__ idx4,
         const float* __restrict__ Wall, const float* __restrict__ ball,
         const float* __restrict__ P4, const float* __restrict__ P3,
         const float* __restrict__ P2, const float* __restrict__ P1,
         const float* __restrict__ P0)
{
    int bid = blockIdx.x, t = threadIdx.x;
    if (bid == 0 && t == 0) g_sync_cnt = 0;
    if (bid < 85) {
        const int* idx; float* dst; int base, M;
        if (bid < 64)      { idx = idx1; dst = g_xyz1; base = bid*256;      M = NL1; }
        else if (bid < 80) { idx = idx2; dst = g_xyz2; base = (bid-64)*256; M = NL2; }
        else if (bid < 84) { idx = idx3; dst = g_xyz3; base = (bid-80)*256; M = NL3; }
        else               { idx = idx4; dst = g_xyz4; base = 0;            M = NL4; }
        int i = base + t;
        if (i < M) {
            int s = idx[i];
            dst[i*3+0] = xyz0[s*3+0]; dst[i*3+1] = xyz0[s*3+1]; dst[i*3+2] = xyz0[s*3+2];
        }
    } else if (bid < 725) {
        int lb = bid - 85;
        int lvl = lb >> 7, sub = lb & 127;
        const float* P = lvl == 0 ? P4 : lvl == 1 ? P3 : lvl == 2 ? P2 : lvl == 3 ? P1 : P0;
        int i = sub * 256 + t;
        int reg = i & 1, T = (i >> 1) & 31, ntg = (i >> 6) & 31, s = (i >> 11) & 1, ch = i >> 12;
        int k = ch*32 + s*16 + (T & 3)*2 + reg*8;
        int n = ntg*8 + (T >> 2);
        __half h0, l0, h1, l1;
        splith(P[k*C + n], h0, l0);
        splith(P[(k+1)*C + n], h1, l1);
        g_Bh16[lvl][i] = packh(h0, h1);
        g_Bl16[lvl][i] = packh(l0, l1);
    } else {
        float w0 = Wall[t], w1 = Wall[C+t], w2 = Wall[2*C+t], bb = ball[t];
        float m = -3.4e38f;
        for (int i = 0; i < NL4; i++) {
            float v = fmaf(xyz0[i*3+0], w0, fmaf(xyz0[i*3+1], w1, fmaf(xyz0[i*3+2], w2, bb)));
            m = fmaxf(m, v);
        }
        g_cls4[t] = m;
    }
}

// =============== K2: fused coef + nn ===============
__global__ void __launch_bounds__(256)
coef_nn(const float* __restrict__ Wall, const float* __restrict__ ball,
        const float* __restrict__ W4, const float* __restrict__ b4,
        const float* __restrict__ W3, const float* __restrict__ b3,
        const float* __restrict__ W2, const float* __restrict__ b2,
        const float* __restrict__ W1, const float* __restrict__ b1,
        const float* __restrict__ W0, const float* __restrict__ b0,
        const float* __restrict__ P4, const float* __restrict__ pb4,
        const float* __restrict__ P3, const float* __restrict__ pb3,
        const float* __restrict__ P2, const float* __restrict__ pb2,
        const float* __restrict__ P1, const float* __restrict__ pb1,
        const float* __restrict__ P0, const float* __restrict__ pb0)
{
    __shared__ float shm[4096];
    int bid = blockIdx.x, t = threadIdx.x;
    if (bid < 40) {
        float (*red)[7][32] = (float(*)[7][32])shm;
        int lvl = bid >> 3, blk = bid & 7;
        const float* W  = lvl==0 ? W4 : lvl==1 ? W3 : lvl==2 ? W2 : lvl==3 ? W1 : W0;
        const float* b  = lvl==0 ? b4 : lvl==1 ? b3 : lvl==2 ? b2 : lvl==3 ? b1 : b0;
        const float* P  = lvl==0 ? P4 : lvl==1 ? P3 : lvl==2 ? P2 : lvl==3 ? P1 : P0;
        const float* pb = lvl==0 ? pb4: lvl==1 ? pb3: lvl==2 ? pb2: lvl==3 ? pb1: pb0;
        int lvl4 = (lvl == 0);
        float* coef = &g_coef[lvl][0];
        int nl = t & 31, sl = t >> 5;
        int n = blk * 32 + nl;
        float a0=0,a1=0,a2=0,a3=0,a4=0,a5=0,a6=0;
        for (int c = sl*32; c < sl*32 + 32; c++) {
            float p1 = P[c*C + n], p2 = P[(256 + c)*C + n];
            a0 = fmaf(W[c], p1, a0);
            a1 = fmaf(W[256 + c], p1, a1);
            a2 = fmaf(W[512 + c], p1, a2);
            a3 = fmaf(Wall[c], p2, a3);
            a4 = fmaf(Wall[256 + c], p2, a4);
            a5 = fmaf(Wall[512 + c], p2, a5);
            float bc = b[c] + (lvl4 ? g_cls4[c] : 0.0f);
            a6 = fmaf(bc, p1, fmaf(ball[c], p2, a6));
        }
        red[sl][0][nl]=a0; red[sl][1][nl]=a1; red[sl][2][nl]=a2; red[sl][3][nl]=a3;
        red[sl][4][nl]=a4; red[sl][5][nl]=a5; red[sl][6][nl]=a6;
        __syncthreads();
        if (t < 224) {
            int o = t >> 5, nn2 = t & 31;
            float s = 0;
            #pragma unroll
            for (int q = 0; q < 8; q++) s += red[q][o][nn2];
            if (o == 6) s += pb[blk*32 + nn2];
            coef[o*256 + blk*32 + nn2] = s;
        }
    } else {
        int nb = bid - 40;
        float* rx = shm; float* ry = shm + 1024; float* rz = shm + 2048; float* rn = shm + 3072;
        const float *q, *ref; int Mr, qbase; int* outv;
        if (nb < 4)       { q = g_xyz3; ref = g_xyz4; Mr = NL4; qbase = nb*256;      outv = g_k34; }
        else if (nb < 20) { q = g_xyz2; ref = g_xyz3; Mr = NL3; qbase = (nb-4)*256;  outv = g_k23; }
        else              { q = g_xyz1; ref = g_xyz2; Mr = NL2; qbase = (nb-20)*256; outv = g_k12; }
        int tid = qbase + t;
        float qx = q[tid*3+0], qy = q[tid*3+1], qz = q[tid*3+2];
        float m2x = -2.f*qx, m2y = -2.f*qy, m2z = -2.f*qz;
        float best[4] = {3.4e38f, 3.4e38f, 3.4e38f, 3.4e38f};
        int bi[4] = {0, 0, 0, 0};
        for (int base = 0; base < Mr; base += 1024) {
            int n = min(1024, Mr - base);
            for (int j = t; j < n; j += 256) {
                float x = ref[(base+j)*3+0], y = ref[(base+j)*3+1], z = ref[(base+j)*3+2];
                rx[j]=x; ry[j]=y; rz[j]=z; rn[j] = x*x + y*y + z*z;
            }
            __syncthreads();
            #pragma unroll 2
            for (int j = 0; j < n; j += 4) {
                #pragma unroll
                for (int u = 0; u < 4; u++) {
                    float d = fmaf(m2x, rx[j+u], fmaf(m2y, ry[j+u], fmaf(m2z, rz[j+u], rn[j+u])));
                    if (d < best[u]) { best[u] = d; bi[u] = base + j + u; }
                }
            }
            __syncthreads();
        }
        float bf = best[0]; int bo = bi[0];
        #pragma unroll
        for (int u = 1; u < 4; u++)
            if (best[u] < bf || (best[u] == bf && bi[u] < bo)) { bf = best[u]; bo = bi[u]; }
        outv[tid] = bo;
    }
}

// =============== persistent GEMM: pe4 + L3..L0, grid barriers between ===============
#define A_STRIDE 36
#define A_LO_W   2304
#define A_BUF_W  4608
#define B_BASE   9216
#define B_SUB_W  4096
#define B_BUF_W  8192
#define SMEMB    ((B_BASE + 2*B_BUF_W) * 4)   // 102400 B

__device__ __forceinline__ void tile64(
    const int* __restrict__ knn, const float* __restrict__ xyzq,
    const float* __restrict__ xyzr, const float* __restrict__ xyz0,
    const float* __restrict__ pe_prev, const uint32_t* __restrict__ Bh,
    const uint32_t* __restrict__ Bl, const float* __restrict__ coef,
    float* __restrict__ out, int bx, int yb, uint32_t* sm, uint32_t sbase)
{
    const int t = threadIdx.x, lane = t & 31, wid = t >> 5;
    const int wm = wid & 1, wn = wid >> 1;
    const int rowbase = bx * 64;
    const int arow = t >> 2, aq = t & 3;
    const int rowg = rowbase + arow;
    const float* prow = pe_prev + (size_t)knn[rowg] * C;

    #define COPY_B(c) do {                                                             \
        const int bb_ = B_BASE + ((c) & 1) * B_BUF_W;                                  \
        _Pragma("unroll")                                                              \
        for (int j_ = 0; j_ < 2; j_++) {                                               \
            const int cc_ = (c)*2 + j_;                                                \
            const uint32_t* s0_ = Bh + (size_t)cc_*4096 + yb*1024 + t*4;               \
            const uint32_t* s1_ = Bl + (size_t)cc_*4096 + yb*1024 + t*4;               \
            _Pragma("unroll")                                                          \
            for (int s_ = 0; s_ < 2; s_++) {                                           \
                asm volatile("cp.async.cg.shared.global [%0], [%1], 16;"               \
                    :: "r"(sbase + 4*(bb_ + j_*B_SUB_W + s_*1024 + t*4)),              \
                       "l"(s0_ + s_*2048) : "memory");                                 \
                asm volatile("cp.async.cg.shared.global [%0], [%1], 16;"               \
                    :: "r"(sbase + 4*(bb_ + j_*B_SUB_W + 2048 + s_*1024 + t*4)),       \
                       "l"(s1_ + s_*2048) : "memory");                                 \
            }                                                                          \
        }                                                                              \
        asm volatile("cp.async.commit_group;" ::: "memory");                           \
    } while (0)

    float4 va0, va1, va2, va3;
    #define LOAD_A(c) do {                                                             \
        int kg_ = (c)*64 + aq*16;                                                      \
        va0 = *(const float4*)(prow + kg_);                                            \
        va1 = *(const float4*)(prow + kg_ + 4);                                        \
        va2 = *(const float4*)(prow + kg_ + 8);                                        \
        va3 = *(const float4*)(prow + kg_ + 12);                                       \
    } while (0)

    #define STORE_A(c) do {                                                            \
        const int ab_ = ((c) & 1) * A_BUF_W;                                           \
        uint32_t hw_[8], lw_[8];                                                       \
        split_pair(va0.x, va0.y, hw_[0], lw_[0]);                                      \
        split_pair(va0.z, va0.w, hw_[1], lw_[1]);                                      \
        split_pair(va1.x, va1.y, hw_[2], lw_[2]);                                      \
        split_pair(va1.z, va1.w, hw_[3], lw_[3]);                                      \
        split_pair(va2.x, va2.y, hw_[4], lw_[4]);                                      \
        split_pair(va2.z, va2.w, hw_[5], lw_[5]);                                      \
        split_pair(va3.x, va3.y, hw_[6], lw_[6]);                                      \
        split_pair(va3.z, va3.w, hw_[7], lw_[7]);                                      \
        uint4* dh_ = (uint4*)&sm[ab_ + arow*A_STRIDE + aq*8];                          \
        dh_[0] = *(uint4*)&hw_[0]; dh_[1] = *(uint4*)&hw_[4];                          \
        uint4* dl_ = (uint4*)&sm[ab_ + A_LO_W + arow*A_STRIDE + aq*8];                 \
        dl_[0] = *(uint4*)&lw_[0]; dl_[1] = *(uint4*)&lw_[4];                          \
    } while (0)

    float d[2][4][4];
    #pragma unroll
    for (int i = 0; i < 2; i++)
        #pragma unroll
        for (int j = 0; j < 4; j++)
            #pragma unroll
            for (int q = 0; q < 4; q++) d[i][j][q] = 0.0f;

    COPY_B(0);
    LOAD_A(0);
    STORE_A(0);
    asm volatile("cp.async.wait_group 0;" ::: "memory");
    __syncthreads();

    const int r0 = lane >> 2, c0 = lane & 3;
    const int lr = (lane & 7) + ((lane >> 3) & 1) * 8;
    const int kseg = (lane >> 4) * 4;

    for (int c = 0; c < 4; c++) {
        if (c < 3) {
            COPY_B(c + 1);
            LOAD_A(c + 1);
        }
        const int ab = (c & 1) * A_BUF_W;
        const int bb = B_BASE + (c & 1) * B_BUF_W;
        #pragma unroll
        for (int s = 0; s < 4; s++) {
            const int sub = s >> 1, sh = s & 1;
            uint32_t Afh[2][4], Afl[2][4];
            #pragma unroll
            for (int tmi = 0; tmi < 2; tmi++) {
                uint32_t aw = sbase + 4*(ab + (wm*32 + tmi*16 + lr)*A_STRIDE + s*8 + kseg);
                LDM4(Afh[tmi], aw);
                LDM4(Afl[tmi], aw + A_LO_W*4);
            }
            uint32_t Bf[4][2];
            #pragma unroll
            for (int nt = 0; nt < 4; nt++) {
                int ntl = wn*4 + nt;
                *(uint2*)Bf[nt] = *(const uint2*)&sm[bb + sub*B_SUB_W + sh*1024 + ntl*64 + lane*2];
            }
            #pragma unroll
            for (int tmi = 0; tmi < 2; tmi++)
                #pragma unroll
                for (int nt = 0; nt < 4; nt++) mma16(d[tmi][nt], Afh[tmi], Bf[nt]);
            #pragma unroll
            for (int tmi = 0; tmi < 2; tmi++)
                #pragma unroll
                for (int nt = 0; nt < 4; nt++) mma16(d[tmi][nt], Afl[tmi], Bf[nt]);
            #pragma unroll
            for (int nt = 0; nt < 4; nt++) {
                int ntl = wn*4 + nt;
                *(uint2*)Bf[nt] = *(const uint2*)&sm[bb + sub*B_SUB_W + 2048 + sh*1024 + ntl*64 + lane*2];
            }
            #pragma unroll
            for (int tmi = 0; tmi < 2; tmi++)
                #pragma unroll
                for (int nt = 0; nt < 4; nt++) mma16(d[tmi][nt], Afh[tmi], Bf[nt]);
        }
        if (c < 3) {
            STORE_A(c + 1);
            asm volatile("cp.async.wait_group 0;" ::: "memory");
        }
        __syncthreads();
    }

    float* cfs = (float*)sm;            // [7][128]
    float* dps = (float*)(sm + 896);    // [6][64]
    if (t < 64) {
        int rge = rowbase + t;
        int kk = knn[rge];
        dps[0*64 + t] = xyzq[rge*3+0] - xyzr[kk*3+0];
        dps[1*64 + t] = xyzq[rge*3+1] - xyzr[kk*3+1];
        dps[2*64 + t] = xyzq[rge*3+2] - xyzr[kk*3+2];
        dps[3*64 + t] = xyz0[rge*3+0];
        dps[4*64 + t] = xyz0[rge*3+1];
        dps[5*64 + t] = xyz0[rge*3+2];
    } else if (t >= 128) {
        int u = t - 128;
        #pragma unroll
        for (int jj = 0; jj < 7; jj++) cfs[jj*128 + u] = coef[jj*256 + yb*128 + u];
    }
    __syncthreads();

    #pragma unroll
    for (int tmi = 0; tmi < 2; tmi++)
        #pragma unroll
        for (int nt = 0; nt < 4; nt++) {
            int rl = wm*32 + tmi*16 + r0;
            int cl = wn*32 + nt*8 + c0*2;
            int rg = rowbase + rl;
            int cg = yb*128 + cl;
            #pragma unroll
            for (int rr = 0; rr < 2; rr++) {
                int rli = rl + rr*8, rgi = rg + rr*8;
                float base0 = cfs[6*128+cl]
                    + dps[0*64+rli]*cfs[0*128+cl] + dps[1*64+rli]*cfs[1*128+cl]
                    + dps[2*64+rli]*cfs[2*128+cl] + dps[3*64+rli]*cfs[3*128+cl]
                    + dps[4*64+rli]*cfs[4*128+cl] + dps[5*64+rli]*cfs[5*128+cl];
                float base1 = cfs[6*128+cl+1]
                    + dps[0*64+rli]*cfs[0*128+cl+1] + dps[1*64+rli]*cfs[1*128+cl+1]
                    + dps[2*64+rli]*cfs[2*128+cl+1] + dps[3*64+rli]*cfs[3*128+cl+1]
                    + dps[4*64+rli]*cfs[4*128+cl+1] + dps[5*64+rli]*cfs[5*128+cl+1];
                *(float2*)(out + (size_t)rgi*C + cg) =
                    make_float2(d[tmi][nt][rr*2+0] + base0, d[tmi][nt][rr*2+1] + base1);
            }
        }
    __syncthreads();     // protect smem reuse by the next tile / barrier
    #undef COPY_B
    #undef LOAD_A
    #undef STORE_A
}

__global__ void __launch_bounds__(256, 2)
pe_persist(const float* __restrict__ xyz0, const int* __restrict__ idx0,
           float* __restrict__ out)
{
    extern __shared__ uint32_t sm[];
    const uint32_t sbase = smem_u32(sm);
    const int t = threadIdx.x;

    // ---- phase 0: pe4 (rank-3 epilogue only) ----
    for (int r = blockIdx.x; r < NL4; r += NCTA) {
        if (t < 128) {
            const float* coef = &g_coef[0][0];
            float dx = g_xyz4[r*3+0], dy = g_xyz4[r*3+1], dz = g_xyz4[r*3+2];
            float x0 = xyz0[r*3+0], y0 = xyz0[r*3+1], z0 = xyz0[r*3+2];
            int c0 = 2*t, c1 = c0 + 1;
            float v0 = coef[6*256+c0] + dx*coef[c0] + dy*coef[256+c0] + dz*coef[512+c0]
                     + x0*coef[3*256+c0] + y0*coef[4*256+c0] + z0*coef[5*256+c0];
            float v1 = coef[6*256+c1] + dx*coef[c1] + dy*coef[256+c1] + dz*coef[512+c1]
                     + x0*coef[3*256+c1] + y0*coef[4*256+c1] + z0*coef[5*256+c1];
            *(float2*)(out + OFF4 + (size_t)r*C + c0) = make_float2(v0, v1);
        }
    }
    grid_sync(NCTA);

    // ---- levels L3..L0 ----
    #pragma unroll 1
    for (int lvl = 0; lvl < 4; lvl++) {
        const int tilesx = 16 << (2*lvl);
        const int* kn = (lvl==0) ? g_k34 : (lvl==1) ? g_k23 : (lvl==2) ? g_k12 : idx0;
        const float* xq = (lvl==0) ? g_xyz3 : (lvl==1) ? g_xyz2 : (lvl==2) ? g_xyz1 : xyz0;
        const float* xr = (lvl==0) ? g_xyz4 : (lvl==1) ? g_xyz3 : (lvl==2) ? g_xyz2 : g_xyz1;
        const float* pp = out + ((lvl==0) ? OFF4 : (lvl==1) ? OFF3 : (lvl==2) ? OFF2 : OFF1);
        float* po = out + ((lvl==0) ? OFF3 : (lvl==1) ? OFF2 : (lvl==2) ? OFF1 : OFF0);
        const uint32_t* bh_ = &g_Bh16[lvl+1][0];
        const uint32_t* bl_ = &g_Bl16[lvl+1][0];
        const float* cf = &g_coef[lvl+1][0];

        for (int job = blockIdx.x; job < 2*tilesx; job += NCTA)
            tile64(kn, xq, xr, xyz0, pp, bh_, bl_, cf, po,
                   job % tilesx, job / tilesx, sm, sbase);

        if (lvl < 3) grid_sync((unsigned)(2 + lvl) * NCTA);
    }
}

// ---------- host ----------
extern "C" void kernel_launch(void* const* d_in, const int* in_sizes, int n_in,
                              void* d_out, int out_size) {
    const float* xyz0 = (const float*)d_in[0];
    const int* idx0 = (const int*)d_in[1];
    const int* idx1 = (const int*)d_in[2];
    const int* idx2 = (const int*)d_in[3];
    const int* idx3 = (const int*)d_in[4];
    const int* idx4 = (const int*)d_in[5];
    const float* W_all = (const float*)d_in[6];
    const float* b_all = (const float*)d_in[7];
    const float* W4 = (const float*)d_in[8];  const float* b4 = (const float*)d_in[9];
    const float* W3 = (const float*)d_in[10]; const float* b3 = (const float*)d_in[11];
    const float* W2 = (const float*)d_in[12]; const float* b2 = (const float*)d_in[13];
    const float* W1 = (const float*)d_in[14]; const float* b1 = (const float*)d_in[15];
    const float* W0 = (const float*)d_in[16]; const float* b0 = (const float*)d_in[17];
    const float* P4 = (const float*)d_in[18]; const float* pb4 = (const float*)d_in[19];
    const float* P3 = (const float*)d_in[20]; const float* pb3 = (const float*)d_in[21];
    const float* P2 = (const float*)d_in[22]; const float* pb2 = (const float*)d_in[23];
    const float* P1 = (const float*)d_in[24]; const float* pb1 = (const float*)d_in[25];
    const float* P0 = (const float*)d_in[26]; const float* pb0 = (const float*)d_in[27];
    float* out = (float*)d_out;

    cudaFuncSetAttribute(pe_persist, cudaFuncAttributeMaxDynamicSharedMemorySize, SMEMB);

    prep_all<<<726, 256>>>(xyz0, idx1, idx2, idx3, idx4, W_all, b_all,
                           P4, P3, P2, P1, P0);
    coef_nn<<<124, 256>>>(W_all, b_all, W4, b4, W3, b3, W2, b2, W1, b1, W0, b0,
                          P4, pb4, P3, pb3, P2, pb2, P1, pb1, P0, pb0);
    pe_persist<<<NCTA, 256, SMEMB>>>(xyz0, idx0, out);
}

// round 17
// speedup vs baseline: 1.0285x; 1.0285x over previous
#include <cuda_runtime.h>
#include <cuda_fp16.h>
#include <cstdint>

#define NL0 65536
#define NL1 16384
#define NL2 4096
#define NL3 1024
#define NL4 256
#define C   256

#define OFF4 0
#define OFF3 (NL4*C)
#define OFF2 (OFF3 + NL3*C)
#define OFF1 (OFF2 + NL2*C)
#define OFF0 (OFF1 + NL1*C)

__device__ uint32_t g_Bh16[5][32768];
__device__ uint32_t g_Bl16[5][32768];
__device__ float g_coef[5][7 * 256];
__device__ float g_cls4[C];
__device__ float g_xyz1[NL1 * 3];
__device__ float g_xyz2[NL2 * 3];
__device__ float g_xyz3[NL3 * 3];
__device__ float g_xyz4[NL4 * 3];
__device__ int   g_k34[NL3];
__device__ int   g_k23[NL2];
__device__ int   g_k12[NL1];

__device__ __forceinline__ uint32_t smem_u32(const void* p) {
    uint32_t a;
    asm("{ .reg .u64 t; cvta.to.shared.u64 t, %1; cvt.u32.u64 %0, t; }" : "=r"(a) : "l"(p));
    return a;
}
__device__ __forceinline__ void splith(float v, __half& h, __half& l) {
    h = __float2half_rn(v);
    l = __float2half_rn(v - __half2float(h));
}
__device__ __forceinline__ uint32_t packh(__half a, __half b) {
    return (uint32_t)__half_as_ushort(a) | ((uint32_t)__half_as_ushort(b) << 16);
}
__device__ __forceinline__ void split_pair(float v0, float v1, uint32_t& h, uint32_t& l) {
    __half2 hh = __float22half2_rn(make_float2(v0, v1));
    float2 bk = __half22float2(hh);
    __half2 ll = __float22half2_rn(make_float2(v0 - bk.x, v1 - bk.y));
    h = *(uint32_t*)&hh; l = *(uint32_t*)&ll;
}
__device__ __forceinline__ void mma16(float* d, const uint32_t* a, const uint32_t* b) {
    asm volatile("mma.sync.aligned.m16n8k16.row.col.f32.f16.f16.f32 "
        "{%0,%1,%2,%3}, {%4,%5,%6,%7}, {%8,%9}, {%0,%1,%2,%3};"
        : "+f"(d[0]), "+f"(d[1]), "+f"(d[2]), "+f"(d[3])
        : "r"(a[0]), "r"(a[1]), "r"(a[2]), "r"(a[3]), "r"(b[0]), "r"(b[1]));
}
#define LDM4(r, a)                                                                  \
    asm volatile("ldmatrix.sync.aligned.m8n8.x4.shared.b16 {%0,%1,%2,%3}, [%4];"    \
        : "=r"((r)[0]), "=r"((r)[1]), "=r"((r)[2]), "=r"((r)[3]) : "r"(a))

// =============== K1: gathers + cls4 (small, fast) ===============
__global__ void __launch_bounds__(256)
prep_gather(const float* __restrict__ xyz0,
            const int* __restrict__ idx1, const int* __restrict__ idx2,
            const int* __restrict__ idx3, const int* __restrict__ idx4,
            const float* __restrict__ Wall, const float* __restrict__ ball)
{
    int bid = blockIdx.x, t = threadIdx.x;
    if (bid < 85) {
        const int* idx; float* dst; int base, M;
        if (bid < 64)      { idx = idx1; dst = g_xyz1; base = bid*256;      M = NL1; }
        else if (bid < 80) { idx = idx2; dst = g_xyz2; base = (bid-64)*256; M = NL2; }
        else if (bid < 84) { idx = idx3; dst = g_xyz3; base = (bid-80)*256; M = NL3; }
        else               { idx = idx4; dst = g_xyz4; base = 0;            M = NL4; }
        int i = base + t;
        if (i < M) {
            int s = idx[i];
            dst[i*3+0] = xyz0[s*3+0]; dst[i*3+1] = xyz0[s*3+1]; dst[i*3+2] = xyz0[s*3+2];
        }
    } else {
        float w0 = Wall[t], w1 = Wall[C+t], w2 = Wall[2*C+t], bb = ball[t];
        float m = -3.4e38f;
        for (int i = 0; i < NL4; i++) {
            float v = fmaf(xyz0[i*3+0], w0, fmaf(xyz0[i*3+1], w1, fmaf(xyz0[i*3+2], w2, bb)));
            m = fmaxf(m, v);
        }
        g_cls4[t] = m;
    }
}

// =============== K2: coef (0-39) + nn (40-123) + prep_B (124-763) ===============
__global__ void __launch_bounds__(256)
coef_nn_prepB(const float* __restrict__ Wall, const float* __restrict__ ball,
        const float* __restrict__ W4, const float* __restrict__ b4,
        const float* __restrict__ W3, const float* __restrict__ b3,
        const float* __restrict__ W2, const float* __restrict__ b2,
        const float* __restrict__ W1, const float* __restrict__ b1,
        const float* __restrict__ W0, const float* __restrict__ b0,
        const float* __restrict__ P4, const float* __restrict__ pb4,
        const float* __restrict__ P3, const float* __restrict__ pb3,
        const float* __restrict__ P2, const float* __restrict__ pb2,
        const float* __restrict__ P1, const float* __restrict__ pb1,
        const float* __restrict__ P0, const float* __restrict__ pb0)
{
    __shared__ float shm[4096];
    int bid = blockIdx.x, t = threadIdx.x;
    if (bid < 40) {
        float (*red)[7][32] = (float(*)[7][32])shm;
        int lvl = bid >> 3, blk = bid & 7;
        const float* W  = lvl==0 ? W4 : lvl==1 ? W3 : lvl==2 ? W2 : lvl==3 ? W1 : W0;
        const float* b  = lvl==0 ? b4 : lvl==1 ? b3 : lvl==2 ? b2 : lvl==3 ? b1 : b0;
        const float* P  = lvl==0 ? P4 : lvl==1 ? P3 : lvl==2 ? P2 : lvl==3 ? P1 : P0;
        const float* pb = lvl==0 ? pb4: lvl==1 ? pb3: lvl==2 ? pb2: lvl==3 ? pb1: pb0;
        int lvl4 = (lvl == 0);
        float* coef = &g_coef[lvl][0];
        int nl = t & 31, sl = t >> 5;
        int n = blk * 32 + nl;
        float a0=0,a1=0,a2=0,a3=0,a4=0,a5=0,a6=0;
        for (int c = sl*32; c < sl*32 + 32; c++) {
            float p1 = P[c*C + n], p2 = P[(256 + c)*C + n];
            a0 = fmaf(W[c], p1, a0);
            a1 = fmaf(W[256 + c], p1, a1);
            a2 = fmaf(W[512 + c], p1, a2);
            a3 = fmaf(Wall[c], p2, a3);
            a4 = fmaf(Wall[256 + c], p2, a4);
            a5 = fmaf(Wall[512 + c], p2, a5);
            float bc = b[c] + (lvl4 ? g_cls4[c] : 0.0f);
            a6 = fmaf(bc, p1, fmaf(ball[c], p2, a6));
        }
        red[sl][0][nl]=a0; red[sl][1][nl]=a1; red[sl][2][nl]=a2; red[sl][3][nl]=a3;
        red[sl][4][nl]=a4; red[sl][5][nl]=a5; red[sl][6][nl]=a6;
        __syncthreads();
        if (t < 224) {
            int o = t >> 5, nn2 = t & 31;
            float s = 0;
            #pragma unroll
            for (int q = 0; q < 8; q++) s += red[q][o][nn2];
            if (o == 6) s += pb[blk*32 + nn2];
            coef[o*256 + blk*32 + nn2] = s;
        }
    } else if (bid < 124) {
        int nb = bid - 40;
        float* rx = shm; float* ry = shm + 1024; float* rz = shm + 2048; float* rn = shm + 3072;
        const float *q, *ref; int Mr, qbase; int* outv;
        if (nb < 4)       { q = g_xyz3; ref = g_xyz4; Mr = NL4; qbase = nb*256;      outv = g_k34; }
        else if (nb < 20) { q = g_xyz2; ref = g_xyz3; Mr = NL3; qbase = (nb-4)*256;  outv = g_k23; }
        else              { q = g_xyz1; ref = g_xyz2; Mr = NL2; qbase = (nb-20)*256; outv = g_k12; }
        int tid = qbase + t;
        float qx = q[tid*3+0], qy = q[tid*3+1], qz = q[tid*3+2];
        float m2x = -2.f*qx, m2y = -2.f*qy, m2z = -2.f*qz;
        float best[4] = {3.4e38f, 3.4e38f, 3.4e38f, 3.4e38f};
        int bi[4] = {0, 0, 0, 0};
        for (int base = 0; base < Mr; base += 1024) {
            int n = min(1024, Mr - base);
            for (int j = t; j < n; j += 256) {
                float x = ref[(base+j)*3+0], y = ref[(base+j)*3+1], z = ref[(base+j)*3+2];
                rx[j]=x; ry[j]=y; rz[j]=z; rn[j] = x*x + y*y + z*z;
            }
            __syncthreads();
            #pragma unroll 2
            for (int j = 0; j < n; j += 4) {
                #pragma unroll
                for (int u = 0; u < 4; u++) {
                    float d = fmaf(m2x, rx[j+u], fmaf(m2y, ry[j+u], fmaf(m2z, rz[j+u], rn[j+u])));
                    if (d < best[u]) { best[u] = d; bi[u] = base + j + u; }
                }
            }
            __syncthreads();
        }
        float bf = best[0]; int bo = bi[0];
        #pragma unroll
        for (int u = 1; u < 4; u++)
            if (best[u] < bf || (best[u] == bf && bi[u] < bo)) { bf = best[u]; bo = bi[u]; }
        outv[tid] = bo;
    } else {
        int lb = bid - 124;
        int lvl = lb >> 7, sub = lb & 127;
        const float* P = lvl == 0 ? P4 : lvl == 1 ? P3 : lvl == 2 ? P2 : lvl == 3 ? P1 : P0;
        int i = sub * 256 + t;
        int reg = i & 1, T = (i >> 1) & 31, ntg = (i >> 6) & 31, s = (i >> 11) & 1, ch = i >> 12;
        int k = ch*32 + s*16 + (T & 3)*2 + reg*8;
        int n = ntg*8 + (T >> 2);
        __half h0, l0, h1, l1;
        splith(P[k*C + n], h0, l0);
        splith(P[(k+1)*C + n], h1, l1);
        g_Bh16[lvl][i] = packh(h0, h1);
        g_Bl16[lvl][i] = packh(l0, l1);
    }
}

// =============== K3: pe4 ===============
__global__ void __launch_bounds__(128)
pe4_kernel(const float* __restrict__ xyz0, float* __restrict__ out4)
{
    int r = blockIdx.x, t = threadIdx.x;
    const float* coef = &g_coef[0][0];
    float dx = g_xyz4[r*3+0], dy = g_xyz4[r*3+1], dz = g_xyz4[r*3+2];
    float x0 = xyz0[r*3+0], y0 = xyz0[r*3+1], z0 = xyz0[r*3+2];
    int c0 = 2*t, c1 = c0 + 1;
    float v0 = coef[6*256+c0] + dx*coef[c0] + dy*coef[256+c0] + dz*coef[512+c0]
             + x0*coef[3*256+c0] + y0*coef[4*256+c0] + z0*coef[5*256+c0];
    float v1 = coef[6*256+c1] + dx*coef[c1] + dy*coef[256+c1] + dz*coef[512+c1]
             + x0*coef[3*256+c1] + y0*coef[4*256+c1] + z0*coef[5*256+c1];
    *(float2*)(out4 + (size_t)r*C + c0) = make_float2(v0, v1);
}

// =============== pe GEMM: template TM ===============
#define A_STRIDE 36
#define B_SUB_W  4096
#define B_BUF_W  8192

template<int TM>
__global__ void __launch_bounds__(256, 2)
pe_mma(const int* __restrict__ knn,
       const float* __restrict__ xyzq, const float* __restrict__ xyzr,
       const float* __restrict__ xyz0, const float* __restrict__ pe_prev,
       const uint32_t* __restrict__ Bh, const uint32_t* __restrict__ Bl,
       const float* __restrict__ coef, float* __restrict__ out)
{
    constexpr int MROWS  = TM * 32;
    constexpr int A_LO_W = MROWS * A_STRIDE;
    constexpr int A_BUF_W = 2 * A_LO_W;
    constexpr int B_BASE  = 2 * A_BUF_W;

    extern __shared__ uint32_t sm[];
    const int t = threadIdx.x, lane = t & 31, wid = t >> 5;
    const int wm = wid & 1, wn = wid >> 1;
    const int rowbase = blockIdx.x * MROWS;
    const int yb = blockIdx.y;
    const uint32_t sbase = smem_u32(sm);

    const int arow = (TM == 2) ? (t >> 2) : (t >> 3);
    const int aq   = (TM == 2) ? (t & 3) : (t & 7);
    const int rowg = rowbase + arow;
    const float* prow = pe_prev + (size_t)knn[rowg] * C;

    #define COPY_B(c) do {                                                             \
        const int bb_ = B_BASE + ((c) & 1) * B_BUF_W;                                  \
        _Pragma("unroll")                                                              \
        for (int j_ = 0; j_ < 2; j_++) {                                               \
            const int cc_ = (c)*2 + j_;                                                \
            const uint32_t* s0_ = Bh + (size_t)cc_*4096 + yb*1024 + t*4;               \
            const uint32_t* s1_ = Bl + (size_t)cc_*4096 + yb*1024 + t*4;               \
            _Pragma("unroll")                                                          \
            for (int s_ = 0; s_ < 2; s_++) {                                           \
                asm volatile("cp.async.cg.shared.global [%0], [%1], 16;"               \
                    :: "r"(sbase + 4*(bb_ + j_*B_SUB_W + s_*1024 + t*4)),              \
                       "l"(s0_ + s_*2048) : "memory");                                 \
                asm volatile("cp.async.cg.shared.global [%0], [%1], 16;"               \
                    :: "r"(sbase + 4*(bb_ + j_*B_SUB_W + 2048 + s_*1024 + t*4)),       \
                       "l"(s1_ + s_*2048) : "memory");                                 \
            }                                                                          \
        }                                                                              \
        asm volatile("cp.async.commit_group;" ::: "memory");                           \
    } while (0)

    float4 va0, va1, va2, va3;
    #define LOAD_A(c) do {                                                             \
        if (TM == 2) {                                                                 \
            int kg_ = (c)*64 + aq*16;                                                  \
            va0 = *(const float4*)(prow + kg_);                                        \
            va1 = *(const float4*)(prow + kg_ + 4);                                    \
            va2 = *(const float4*)(prow + kg_ + 8);                                    \
            va3 = *(const float4*)(prow + kg_ + 12);                                   \
        } else {                                                                       \
            int kg_ = (c)*64 + aq*8;                                                   \
            va0 = *(const float4*)(prow + kg_);                                        \
            va1 = *(const float4*)(prow + kg_ + 4);                                    \
        }                                                                              \
    } while (0)

    #define STORE_A(c) do {                                                            \
        const int ab_ = ((c) & 1) * A_BUF_W;                                           \
        if (TM == 2) {                                                                 \
            uint32_t hw_[8], lw_[8];                                                   \
            split_pair(va0.x, va0.y, hw_[0], lw_[0]);                                  \
            split_pair(va0.z, va0.w, hw_[1], lw_[1]);                                  \
            split_pair(va1.x, va1.y, hw_[2], lw_[2]);                                  \
            split_pair(va1.z, va1.w, hw_[3], lw_[3]);                                  \
            split_pair(va2.x, va2.y, hw_[4], lw_[4]);                                  \
            split_pair(va2.z, va2.w, hw_[5], lw_[5]);                                  \
            split_pair(va3.x, va3.y, hw_[6], lw_[6]);                                  \
            split_pair(va3.z, va3.w, hw_[7], lw_[7]);                                  \
            uint4* dh_ = (uint4*)&sm[ab_ + arow*A_STRIDE + aq*8];                      \
            dh_[0] = *(uint4*)&hw_[0]; dh_[1] = *(uint4*)&hw_[4];                      \
            uint4* dl_ = (uint4*)&sm[ab_ + A_LO_W + arow*A_STRIDE + aq*8];             \
            dl_[0] = *(uint4*)&lw_[0]; dl_[1] = *(uint4*)&lw_[4];                      \
        } else {                                                                       \
            uint32_t hw_[4], lw_[4];                                                   \
            split_pair(va0.x, va0.y, hw_[0], lw_[0]);                                  \
            split_pair(va0.z, va0.w, hw_[1], lw_[1]);                                  \
            split_pair(va1.x, va1.y, hw_[2], lw_[2]);                                  \
            split_pair(va1.z, va1.w, hw_[3], lw_[3]);                                  \
            *(uint4*)&sm[ab_ + arow*A_STRIDE + aq*4] = *(uint4*)hw_;                   \
            *(uint4*)&sm[ab_ + A_LO_W + arow*A_STRIDE + aq*4] = *(uint4*)lw_;          \
        }                                                                              \
    } while (0)

    float d[TM][4][4];
    #pragma unroll
    for (int i = 0; i < TM; i++)
        #pragma unroll
        for (int j = 0; j < 4; j++)
            #pragma unroll
            for (int q = 0; q < 4; q++) d[i][j][q] = 0.0f;

    COPY_B(0);
    LOAD_A(0);
    STORE_A(0);
    asm volatile("cp.async.wait_group 0;" ::: "memory");
    __syncthreads();

    const int r0 = lane >> 2, c0 = lane & 3;
    const int lr = (lane & 7) + ((lane >> 3) & 1) * 8;
    const int kseg = (lane >> 4) * 4;

    for (int c = 0; c < 4; c++) {
        if (c < 3) {
            COPY_B(c + 1);
            LOAD_A(c + 1);
        }

        const int ab = (c & 1) * A_BUF_W;
        const int bb = B_BASE + (c & 1) * B_BUF_W;
        #pragma unroll
        for (int s = 0; s < 4; s++) {
            const int sub = s >> 1, sh = s & 1;
            uint32_t Afh[TM][4], Afl[TM][4];
            #pragma unroll
            for (int tmi = 0; tmi < TM; tmi++) {
                uint32_t aw = sbase + 4*(ab + (wm*(TM*16) + tmi*16 + lr)*A_STRIDE + s*8 + kseg);
                LDM4(Afh[tmi], aw);
                LDM4(Afl[tmi], aw + A_LO_W*4);
            }
            uint32_t Bf[4][2];
            #pragma unroll
            for (int nt = 0; nt < 4; nt++) {
                int ntl = wn*4 + nt;
                *(uint2*)Bf[nt] = *(const uint2*)&sm[bb + sub*B_SUB_W + sh*1024 + ntl*64 + lane*2];
            }
            #pragma unroll
            for (int tmi = 0; tmi < TM; tmi++)
                #pragma unroll
                for (int nt = 0; nt < 4; nt++) mma16(d[tmi][nt], Afh[tmi], Bf[nt]);
            #pragma unroll
            for (int tmi = 0; tmi < TM; tmi++)
                #pragma unroll
                for (int nt = 0; nt < 4; nt++) mma16(d[tmi][nt], Afl[tmi], Bf[nt]);
            #pragma unroll
            for (int nt = 0; nt < 4; nt++) {
                int ntl = wn*4 + nt;
                *(uint2*)Bf[nt] = *(const uint2*)&sm[bb + sub*B_SUB_W + 2048 + sh*1024 + ntl*64 + lane*2];
            }
            #pragma unroll
            for (int tmi = 0; tmi < TM; tmi++)
                #pragma unroll
                for (int nt = 0; nt < 4; nt++) mma16(d[tmi][nt], Afh[tmi], Bf[nt]);
        }

        if (c < 3) {
            STORE_A(c + 1);
            asm volatile("cp.async.wait_group 0;" ::: "memory");
        }
        __syncthreads();
    }

    float* cfs = (float*)sm;                 // [7][128]
    float* dps = (float*)(sm + 896);         // [6][MROWS]
    if (t < MROWS) {
        int rge = rowbase + t;
        int kk = knn[rge];
        dps[0*MROWS + t] = xyzq[rge*3+0] - xyzr[kk*3+0];
        dps[1*MROWS + t] = xyzq[rge*3+1] - xyzr[kk*3+1];
        dps[2*MROWS + t] = xyzq[rge*3+2] - xyzr[kk*3+2];
        dps[3*MROWS + t] = xyz0[rge*3+0];
        dps[4*MROWS + t] = xyz0[rge*3+1];
        dps[5*MROWS + t] = xyz0[rge*3+2];
    } else if (t >= 128) {
        int u = t - 128;
        #pragma unroll
        for (int jj = 0; jj < 7; jj++) cfs[jj*128 + u] = coef[jj*256 + yb*128 + u];
    }
    __syncthreads();

    #pragma unroll
    for (int tmi = 0; tmi < TM; tmi++)
        #pragma unroll
        for (int nt = 0; nt < 4; nt++) {
            int rl = wm*(TM*16) + tmi*16 + r0;
            int cl = wn*32 + nt*8 + c0*2;
            int rg = rowbase + rl;
            int cg = yb*128 + cl;
            #pragma unroll
            for (int rr = 0; rr < 2; rr++) {
                int rli = rl + rr*8, rgi = rg + rr*8;
                float base0 = cfs[6*128+cl]
                    + dps[0*MROWS+rli]*cfs[0*128+cl] + dps[1*MROWS+rli]*cfs[1*128+cl]
                    + dps[2*MROWS+rli]*cfs[2*128+cl] + dps[3*MROWS+rli]*cfs[3*128+cl]
                    + dps[4*MROWS+rli]*cfs[4*128+cl] + dps[5*MROWS+rli]*cfs[5*128+cl];
                float base1 = cfs[6*128+cl+1]
                    + dps[0*MROWS+rli]*cfs[0*128+cl+1] + dps[1*MROWS+rli]*cfs[1*128+cl+1]
                    + dps[2*MROWS+rli]*cfs[2*128+cl+1] + dps[3*MROWS+rli]*cfs[3*128+cl+1]
                    + dps[4*MROWS+rli]*cfs[4*128+cl+1] + dps[5*MROWS+rli]*cfs[5*128+cl+1];
                *(float2*)(out + (size_t)rgi*C + cg) =
                    make_float2(d[tmi][nt][rr*2+0] + base0, d[tmi][nt][rr*2+1] + base1);
            }
        }
}

#define SMEMB2 ((2*2*64*A_STRIDE + 2*B_BUF_W) * 4)
#define SMEMB1 ((2*2*32*A_STRIDE + 2*B_BUF_W) * 4)

// ---------- host ----------
extern "C" void kernel_launch(void* const* d_in, const int* in_sizes, int n_in,
                              void* d_out, int out_size) {
    const float* xyz0 = (const float*)d_in[0];
    const int* idx0 = (const int*)d_in[1];
    const int* idx1 = (const int*)d_in[2];
    const int* idx2 = (const int*)d_in[3];
    const int* idx3 = (const int*)d_in[4];
    const int* idx4 = (const int*)d_in[5];
    const float* W_all = (const float*)d_in[6];
    const float* b_all = (const float*)d_in[7];
    const float* W4 = (const float*)d_in[8];  const float* b4 = (const float*)d_in[9];
    const float* W3 = (const float*)d_in[10]; const float* b3 = (const float*)d_in[11];
    const float* W2 = (const float*)d_in[12]; const float* b2 = (const float*)d_in[13];
    const float* W1 = (const float*)d_in[14]; const float* b1 = (const float*)d_in[15];
    const float* W0 = (const float*)d_in[16]; const float* b0 = (const float*)d_in[17];
    const float* P4 = (const float*)d_in[18]; const float* pb4 = (const float*)d_in[19];
    const float* P3 = (const float*)d_in[20]; const float* pb3 = (const float*)d_in[21];
    const float* P2 = (const float*)d_in[22]; const float* pb2 = (const float*)d_in[23];
    const float* P1 = (const float*)d_in[24]; const float* pb1 = (const float*)d_in[25];
    const float* P0 = (const float*)d_in[26]; const float* pb0 = (const float*)d_in[27];
    float* out = (float*)d_out;

    float *x1, *x2, *x3, *x4, *coef;
    uint32_t *bh, *bl;
    int *k34, *k23, *k12;
    cudaGetSymbolAddress((void**)&x1, g_xyz1);
    cudaGetSymbolAddress((void**)&x2, g_xyz2);
    cudaGetSymbolAddress((void**)&x3, g_xyz3);
    cudaGetSymbolAddress((void**)&x4, g_xyz4);
    cudaGetSymbolAddress((void**)&k34, g_k34);
    cudaGetSymbolAddress((void**)&k23, g_k23);
    cudaGetSymbolAddress((void**)&k12, g_k12);
    cudaGetSymbolAddress((void**)&bh, g_Bh16);
    cudaGetSymbolAddress((void**)&bl, g_Bl16);
    cudaGetSymbolAddress((void**)&coef, g_coef);

    cudaFuncSetAttribute(pe_mma<2>, cudaFuncAttributeMaxDynamicSharedMemorySize, SMEMB2);
    cudaFuncSetAttribute(pe_mma<1>, cudaFuncAttributeMaxDynamicSharedMemorySize, SMEMB1);

    prep_gather<<<86, 256>>>(xyz0, idx1, idx2, idx3, idx4, W_all, b_all);
    coef_nn_prepB<<<764, 256>>>(W_all, b_all, W4, b4, W3, b3, W2, b2, W1, b1, W0, b0,
                                P4, pb4, P3, pb3, P2, pb2, P1, pb1, P0, pb0);
    pe4_kernel<<<NL4, 128>>>(xyz0, out + OFF4);

    pe_mma<1><<<dim3(NL3/32, 2), 256, SMEMB1>>>(k34, x3, x4, xyz0, out + OFF4,
        bh + 1*(size_t)32768, bl + 1*(size_t)32768, coef + 1*(size_t)7*256, out + OFF3);
    pe_mma<1><<<dim3(NL2/32, 2), 256, SMEMB1>>>(k23, x2, x3, xyz0, out + OFF3,
        bh + 2*(size_t)32768, bl + 2*(size_t)32768, coef + 2*(size_t)7*256, out + OFF2);
    pe_mma<2><<<dim3(NL1/64, 2), 256, SMEMB2>>>(k12, x1, x2, xyz0, out + OFF2,
        bh + 3*(size_t)32768, bl + 3*(size_t)32768, coef + 3*(size_t)7*256, out + OFF1);
    pe_mma<2><<<dim3(NL0/64, 2), 256, SMEMB2>>>(idx0, xyz0, x1, xyz0, out + OFF1,
        bh + 4*(size_t)32768, bl + 4*(size_t)32768, coef + 4*(size_t)7*256, out + OFF0);
}